// round 1
// baseline (speedup 1.0000x reference)
#include <cuda_runtime.h>

#define TT 512
#define BB 256

// Inter-layer activation buffers (written once, read once per launch; guarded by flags)
__device__ float buf1[32][TT][BB][4];    //  67 MB
__device__ float buf2[64][TT][BB][8];    // 268 MB
__device__ float buf3[63][TT][BB][16];   // 529 MB
__device__ int prog1[32];
__device__ int prog2[64];
__device__ int prog3[64][4];

struct P27 { const float* p[27]; };

__device__ __forceinline__ int ld_acq(const int* p) {
    int v;
    asm volatile("ld.acquire.gpu.u32 %0, [%1];" : "=r"(v) : "l"(p) : "memory");
    return v;
}
__device__ __forceinline__ void st_rel(int* p, int v) {
    asm volatile("st.release.gpu.u32 [%0], %1;" :: "l"(p), "r"(v) : "memory");
}

__device__ __forceinline__ float sigf(float x) {
    return __fdividef(1.0f, 1.0f + __expf(-x));
}
__device__ __forceinline__ float tanhfast(float x) {
    // 1 - 2/(e^(2x)+1); exact at +-inf, ~1e-6 rel err elsewhere
    return 1.0f - __fdividef(2.0f, __expf(2.0f * x) + 1.0f);
}

// ---------------- Stack 1: H=4, thread = one batch element, full B=256 ----------------
template <int DIN>
__device__ void run_stack1(const float* Wih, const float* Whh,
                           const float* bih, const float* bhh,
                           const float* xin, int layer, float* smem)
{
    const int G = 16;
    float* sWih = smem;                 // G*DIN
    float* sWhh = smem + G * DIN;       // G*4
    float* sb   = sWhh + G * 4;         // G
    int tid = threadIdx.x;
    for (int i = tid; i < G * DIN; i += 256) sWih[i] = Wih[i];
    for (int i = tid; i < G * 4;   i += 256) sWhh[i] = Whh[i];
    if (tid < G) sb[tid] = bih[tid] + bhh[tid];
    __syncthreads();

    float h[4] = {0,0,0,0}, c[4] = {0,0,0,0};
    const int b = tid;
    const int* flag = (layer > 0) ? &prog1[layer - 1] : (const int*)0;
    int avail = 0;

    for (int t = 0; t < TT; t++) {
        if (flag && avail <= t) { do { avail = ld_acq(flag); } while (avail <= t); }
        float xv[DIN];
        const float* xp = (layer == 0) ? (xin + (t * BB + b) * 2)
                                       : &buf1[layer - 1][t][b][0];
        #pragma unroll
        for (int k = 0; k < DIN; k++) xv[k] = xp[k];

        float hn[4];
        #pragma unroll
        for (int u = 0; u < 4; u++) {
            float ai = sb[u], af = sb[4 + u], ag = sb[8 + u], ao = sb[12 + u];
            #pragma unroll
            for (int k = 0; k < DIN; k++) {
                float xk = xv[k];
                ai += xk * sWih[u * DIN + k];
                af += xk * sWih[(4 + u) * DIN + k];
                ag += xk * sWih[(8 + u) * DIN + k];
                ao += xk * sWih[(12 + u) * DIN + k];
            }
            #pragma unroll
            for (int k = 0; k < 4; k++) {
                float hk = h[k];
                ai += hk * sWhh[u * 4 + k];
                af += hk * sWhh[(4 + u) * 4 + k];
                ag += hk * sWhh[(8 + u) * 4 + k];
                ao += hk * sWhh[(12 + u) * 4 + k];
            }
            float cc = sigf(af) * c[u] + sigf(ai) * tanhfast(ag);
            c[u] = cc;
            hn[u] = sigf(ao) * tanhfast(cc);
        }
        #pragma unroll
        for (int u = 0; u < 4; u++) h[u] = hn[u];
        *(float4*)&buf1[layer][t][b][0] = make_float4(hn[0], hn[1], hn[2], hn[3]);
        __threadfence();
        __syncthreads();
        if (tid == 0) st_rel(&prog1[layer], t + 1);
    }
}

// ---------------- Stack 2: H=8, thread = one batch element, full B=256 ----------------
template <int DIN, bool RELU>
__device__ void run_stack2(const float* Wih, const float* Whh,
                           const float* bih, const float* bhh,
                           int layer, float* smem)
{
    const int G = 32;
    float* sWih = smem;
    float* sWhh = smem + G * DIN;
    float* sb   = sWhh + G * 8;
    int tid = threadIdx.x;
    for (int i = tid; i < G * DIN; i += 256) sWih[i] = Wih[i];
    for (int i = tid; i < G * 8;   i += 256) sWhh[i] = Whh[i];
    if (tid < G) sb[tid] = bih[tid] + bhh[tid];
    __syncthreads();

    float h[8] = {0,0,0,0,0,0,0,0}, c[8] = {0,0,0,0,0,0,0,0};
    const int b = tid;
    const int* flag = (layer == 0) ? &prog1[31] : &prog2[layer - 1];
    int avail = 0;

    for (int t = 0; t < TT; t++) {
        if (avail <= t) { do { avail = ld_acq(flag); } while (avail <= t); }
        float xv[DIN];
        const float* xp = (layer == 0) ? &buf1[31][t][b][0] : &buf2[layer - 1][t][b][0];
        #pragma unroll
        for (int k = 0; k < DIN; k++) {
            float v = xp[k];
            xv[k] = RELU ? fmaxf(v, 0.0f) : v;
        }
        float hn[8];
        #pragma unroll
        for (int u = 0; u < 8; u++) {
            float ai = sb[u], af = sb[8 + u], ag = sb[16 + u], ao = sb[24 + u];
            #pragma unroll
            for (int k = 0; k < DIN; k++) {
                float xk = xv[k];
                ai += xk * sWih[u * DIN + k];
                af += xk * sWih[(8 + u) * DIN + k];
                ag += xk * sWih[(16 + u) * DIN + k];
                ao += xk * sWih[(24 + u) * DIN + k];
            }
            #pragma unroll
            for (int k = 0; k < 8; k++) {
                float hk = h[k];
                ai += hk * sWhh[u * 8 + k];
                af += hk * sWhh[(8 + u) * 8 + k];
                ag += hk * sWhh[(16 + u) * 8 + k];
                ao += hk * sWhh[(24 + u) * 8 + k];
            }
            float cc = sigf(af) * c[u] + sigf(ai) * tanhfast(ag);
            c[u] = cc;
            hn[u] = sigf(ao) * tanhfast(cc);
        }
        float4* dst = (float4*)&buf2[layer][t][b][0];
        dst[0] = make_float4(hn[0], hn[1], hn[2], hn[3]);
        dst[1] = make_float4(hn[4], hn[5], hn[6], hn[7]);
        #pragma unroll
        for (int u = 0; u < 8; u++) h[u] = hn[u];
        __threadfence();
        __syncthreads();
        if (tid == 0) st_rel(&prog2[layer], t + 1);
    }
}

// ------- Stack 3: H=16, block = 64-batch slice, 4 threads/batch (4 units each) -------
template <int DIN, bool RELU, bool LAST>
__device__ void run_stack3(const float* Wih, const float* Whh,
                           const float* bih, const float* bhh,
                           int layer, int slice, float* smem,
                           const float* fcW, const float* fcb, float* out)
{
    const int G = 64, XP = DIN + 1;
    float* sWih = smem;                   // 64*DIN
    float* sWhh = sWih + G * DIN;         // 1024
    float* sb   = sWhh + G * 16;          // 64
    float* xs   = sb + G;                 // 64*XP  layout [b][k] padded
    float* hs   = xs + 64 * XP;           // 64*17  layout [b][k] padded
    float* sfc  = hs + 64 * 17;           // 68 (LAST only)
    int tid = threadIdx.x;
    int b = tid & 63, ug = tid >> 6;

    for (int i = tid; i < G * DIN; i += 256) sWih[i] = Wih[i];
    for (int i = tid; i < G * 16;  i += 256) sWhh[i] = Whh[i];
    if (tid < G) sb[tid] = bih[tid] + bhh[tid];
    if (LAST) {
        if (tid < 64) sfc[tid] = fcW[tid];
        if (tid < 4)  sfc[64 + tid] = fcb[tid];
    }
    for (int i = tid; i < 64 * 17; i += 256) hs[i] = 0.0f;
    __syncthreads();

    float c[4] = {0,0,0,0};
    const int b0 = slice * 64;
    const int* flag = (layer == 0) ? &prog2[63] : &prog3[layer - 1][slice];
    int avail = 0;

    for (int t = 0; t < TT; t++) {
        if (avail <= t) { do { avail = ld_acq(flag); } while (avail <= t); }
        // cooperative input load -> xs[b][k] (padded)
        const float* src = (layer == 0) ? &buf2[63][t][b0][0] : &buf3[layer - 1][t][b0][0];
        for (int i = tid; i < 64 * DIN; i += 256) {
            float v = src[i];
            if (RELU) v = fmaxf(v, 0.0f);
            xs[(i / DIN) * XP + (i % DIN)] = v;
        }
        // capture previous h before it gets overwritten
        float hr[16];
        #pragma unroll
        for (int k = 0; k < 16; k++) hr[k] = hs[b * 17 + k];
        __syncthreads();   // xs ready, hr captured everywhere

        float xr[DIN];
        #pragma unroll
        for (int k = 0; k < DIN; k++) xr[k] = xs[b * XP + k];

        float hn[4];
        #pragma unroll
        for (int v = 0; v < 4; v++) {
            int u = ug * 4 + v;
            float ai = sb[u], af = sb[16 + u], ag = sb[32 + u], ao = sb[48 + u];
            #pragma unroll
            for (int k = 0; k < DIN; k++) {
                float xk = xr[k];
                ai += xk * sWih[u * DIN + k];
                af += xk * sWih[(16 + u) * DIN + k];
                ag += xk * sWih[(32 + u) * DIN + k];
                ao += xk * sWih[(48 + u) * DIN + k];
            }
            #pragma unroll
            for (int k = 0; k < 16; k++) {
                float hk = hr[k];
                ai += hk * sWhh[u * 16 + k];
                af += hk * sWhh[(16 + u) * 16 + k];
                ag += hk * sWhh[(32 + u) * 16 + k];
                ao += hk * sWhh[(48 + u) * 16 + k];
            }
            float cc = sigf(af) * c[v] + sigf(ai) * tanhfast(ag);
            c[v] = cc;
            hn[v] = sigf(ao) * tanhfast(cc);
        }
        #pragma unroll
        for (int v = 0; v < 4; v++) hs[b * 17 + ug * 4 + v] = hn[v];

        if (LAST) {
            __syncthreads();   // hs complete
            if (tid < 64) {
                float o[4];
                #pragma unroll
                for (int m = 0; m < 4; m++) o[m] = sfc[64 + m];
                #pragma unroll
                for (int k = 0; k < 16; k++) {
                    float hv = fmaxf(hs[tid * 17 + k], 0.0f);
                    #pragma unroll
                    for (int m = 0; m < 4; m++) o[m] += hv * sfc[m * 16 + k];
                }
                *(float4*)&out[(t * BB + b0 + tid) * 4] =
                    make_float4(o[0], o[1], o[2], o[3]);
            }
            __syncthreads();
        } else {
            *(float4*)&buf3[layer][t][b0 + b][ug * 4] =
                make_float4(hn[0], hn[1], hn[2], hn[3]);
            __threadfence();
            __syncthreads();
            if (tid == 0) st_rel(&prog3[layer][slice], t + 1);
        }
    }
}

// ---------------- dispatch ----------------
__global__ void __launch_bounds__(256, 3) lstm_pipe(P27 P, float* out)
{
    __shared__ float smem[4360];
    int bid = blockIdx.x;
    if (bid < 32) {
        int l = bid;
        if (l == 0)
            run_stack1<2>(P.p[1], P.p[2], P.p[3], P.p[4], P.p[0], 0, smem);
        else
            run_stack1<4>(P.p[5] + (l - 1) * 64, P.p[6] + (l - 1) * 64,
                          P.p[7] + (l - 1) * 16, P.p[8] + (l - 1) * 16,
                          (const float*)0, l, smem);
    } else if (bid < 96) {
        int l = bid - 32;
        if (l == 0)
            run_stack2<4, true>(P.p[9], P.p[10], P.p[11], P.p[12], 0, smem);
        else
            run_stack2<8, false>(P.p[13] + (l - 1) * 256, P.p[14] + (l - 1) * 256,
                                 P.p[15] + (l - 1) * 32, P.p[16] + (l - 1) * 32,
                                 l, smem);
    } else {
        int idx = bid - 96;
        int l = idx >> 2, s = idx & 3;
        if (l == 0)
            run_stack3<8, true, false>(P.p[17], P.p[18], P.p[19], P.p[20],
                                       0, s, smem, (const float*)0, (const float*)0, (float*)0);
        else if (l < 63)
            run_stack3<16, false, false>(P.p[21] + (l - 1) * 1024, P.p[22] + (l - 1) * 1024,
                                         P.p[23] + (l - 1) * 64, P.p[24] + (l - 1) * 64,
                                         l, s, smem, (const float*)0, (const float*)0, (float*)0);
        else
            run_stack3<16, false, true>(P.p[21] + 62 * 1024, P.p[22] + 62 * 1024,
                                        P.p[23] + 62 * 64, P.p[24] + 62 * 64,
                                        63, s, smem, P.p[25], P.p[26], out);
    }
}

__global__ void reset_progress()
{
    int i = threadIdx.x;
    if (i < 32) prog1[i] = 0;
    if (i < 64) prog2[i] = 0;
    ((int*)prog3)[i] = 0;   // 256 entries
}

extern "C" void kernel_launch(void* const* d_in, const int* in_sizes, int n_in,
                              void* d_out, int out_size)
{
    P27 P;
    for (int i = 0; i < 27; i++) P.p[i] = (const float*)d_in[i];
    reset_progress<<<1, 256>>>();
    lstm_pipe<<<352, 256>>>(P, (float*)d_out);
}

// round 5
// speedup vs baseline: 1.3101x; 1.3101x over previous
#include <cuda_runtime.h>

#define TT 512
typedef unsigned long long u64;

// Packed inter-layer buffers: [layer][t][pair][k] as f32x2 {batch 2p, 2p+1}
__device__ u64 buf1[32][TT][128][4];     //  67 MB
__device__ u64 buf2[64][TT][128][8];     // 268 MB
__device__ u64 buf3[63][TT][128][16];    // 528 MB
__device__ int prog1[32];
__device__ int prog2[64];
__device__ int prog3[64][4];

struct P27 { const float* p[27]; };

__device__ __forceinline__ int ld_acq(const int* p) {
    int v;
    asm volatile("ld.acquire.gpu.u32 %0, [%1];" : "=r"(v) : "l"(p) : "memory");
    return v;
}
__device__ __forceinline__ void st_rel(int* p, int v) {
    asm volatile("st.release.gpu.u32 [%0], %1;" :: "l"(p), "r"(v) : "memory");
}

__device__ __forceinline__ u64 ffma2(u64 a, u64 b, u64 c) {
    u64 d;
    asm("fma.rn.f32x2 %0, %1, %2, %3;" : "=l"(d) : "l"(a), "l"(b), "l"(c));
    return d;
}
__device__ __forceinline__ u64 pack2(float lo, float hi) {
    u64 d;
    asm("mov.b64 %0, {%1, %2};" : "=l"(d) : "f"(lo), "f"(hi));
    return d;
}
__device__ __forceinline__ void unpack2(u64 a, float& x, float& y) {
    asm("mov.b64 {%0, %1}, %2;" : "=f"(x), "=f"(y) : "l"(a));
}

__device__ __forceinline__ float sigf(float x) {
    return __fdividef(1.0f, 1.0f + __expf(-x));
}
__device__ __forceinline__ float tanhfast(float x) {
    return 1.0f - __fdividef(2.0f, __expf(2.0f * x) + 1.0f);
}
__device__ __forceinline__ u64 lstm_pair(u64 ai, u64 af, u64 ag, u64 ao,
                                         float& ca, float& cb) {
    float i0,i1,f0,f1,g0,g1,o0,o1;
    unpack2(ai,i0,i1); unpack2(af,f0,f1); unpack2(ag,g0,g1); unpack2(ao,o0,o1);
    float c0 = sigf(f0) * ca + sigf(i0) * tanhfast(g0);
    float c1 = sigf(f1) * cb + sigf(i1) * tanhfast(g1);
    ca = c0; cb = c1;
    return pack2(sigf(o0) * tanhfast(c0), sigf(o1) * tanhfast(c1));
}

// Stage weights into smem, gate-grouped & duplicated:
// s[(u*DIN + k)*4 + g] = {w,w} with w = W[(g*H + u)*DIN + k]
template <int H, int DIN>
__device__ void stage_w(const float* W, u64* s, int tid) {
    for (int i = tid; i < 4 * H * DIN; i += 128) {
        int r = i / DIN, k = i - r * DIN;
        int g = r / H,  u = r - g * H;
        float w = W[i];
        s[(u * DIN + k) * 4 + g] = pack2(w, w);
    }
}
template <int H>
__device__ void stage_b(const float* bih, const float* bhh, u64* s, int tid) {
    for (int i = tid; i < 4 * H; i += 128) {
        int g = i / H, u = i - g * H;
        float b = bih[i] + bhh[i];
        s[u * 4 + g] = pack2(b, b);
    }
}

// ---------------- Stack 1: H=4, 128 threads, thread = batch pair ----------------
template <int DIN, bool L0>
__device__ void run_stack1(const float* Wih, const float* Whh,
                           const float* bih, const float* bhh,
                           const float* xin, int layer, u64* sm)
{
    const int H = 4;
    u64* sW = sm;
    u64* sU = sW + H * DIN * 4;
    u64* sB = sU + H * H * 4;
    int tid = threadIdx.x;
    stage_w<H, DIN>(Wih, sW, tid);
    stage_w<H, H>(Whh, sU, tid);
    stage_b<H>(bih, bhh, sB, tid);
    __syncthreads();

    u64 h2[H];
    float cA[H], cB[H];
    #pragma unroll
    for (int u = 0; u < H; u++) { h2[u] = 0ull; cA[u] = 0.f; cB[u] = 0.f; }

    const int* fin = L0 ? (const int*)0 : &prog1[layer - 1];
    int* fout = &prog1[layer];
    int avail = 0;

    for (int t = 0; t < TT; t++) {
        if (!L0) {
            if (tid == 0) { while (avail <= t) avail = ld_acq(fin); }
            __syncthreads();
        }
        u64 xv[DIN];
        if (L0) {
            float2 a = *(const float2*)(xin + (t * 256 + 2 * tid) * 2);
            float2 b = *(const float2*)(xin + (t * 256 + 2 * tid + 1) * 2);
            xv[0] = pack2(a.x, b.x); xv[1] = pack2(a.y, b.y);
        } else {
            ulonglong2 r0 = *(ulonglong2*)&buf1[layer - 1][t][tid][0];
            ulonglong2 r1 = *(ulonglong2*)&buf1[layer - 1][t][tid][2];
            xv[0] = r0.x; xv[1] = r0.y;
            if (DIN == 4) { xv[2] = r1.x; xv[3] = r1.y; }
        }
        u64 hn[H];
        #pragma unroll
        for (int u = 0; u < H; u++) {
            ulonglong2 b01 = *(ulonglong2*)&sB[u * 4];
            ulonglong2 b23 = *(ulonglong2*)&sB[u * 4 + 2];
            u64 ai = b01.x, af = b01.y, ag = b23.x, ao = b23.y;
            #pragma unroll
            for (int k = 0; k < DIN; k++) {
                ulonglong2 w01 = *(ulonglong2*)&sW[(u * DIN + k) * 4];
                ulonglong2 w23 = *(ulonglong2*)&sW[(u * DIN + k) * 4 + 2];
                ai = ffma2(xv[k], w01.x, ai); af = ffma2(xv[k], w01.y, af);
                ag = ffma2(xv[k], w23.x, ag); ao = ffma2(xv[k], w23.y, ao);
            }
            #pragma unroll
            for (int k = 0; k < H; k++) {
                ulonglong2 w01 = *(ulonglong2*)&sU[(u * H + k) * 4];
                ulonglong2 w23 = *(ulonglong2*)&sU[(u * H + k) * 4 + 2];
                ai = ffma2(h2[k], w01.x, ai); af = ffma2(h2[k], w01.y, af);
                ag = ffma2(h2[k], w23.x, ag); ao = ffma2(h2[k], w23.y, ao);
            }
            hn[u] = lstm_pair(ai, af, ag, ao, cA[u], cB[u]);
        }
        #pragma unroll
        for (int u = 0; u < H; u++) h2[u] = hn[u];
        *(ulonglong2*)&buf1[layer][t][tid][0] = make_ulonglong2(hn[0], hn[1]);
        *(ulonglong2*)&buf1[layer][t][tid][2] = make_ulonglong2(hn[2], hn[3]);
        __syncthreads();
        if (tid == 0) { __threadfence(); st_rel(fout, t + 1); }
    }
}

// ---------------- Stack 2: H=8, 128 threads, thread = batch pair ----------------
template <int DIN, bool L0>
__device__ void run_stack2(const float* Wih, const float* Whh,
                           const float* bih, const float* bhh,
                           int layer, u64* sm)
{
    const int H = 8;
    u64* sW = sm;
    u64* sU = sW + H * DIN * 4;
    u64* sB = sU + H * H * 4;
    int tid = threadIdx.x;
    stage_w<H, DIN>(Wih, sW, tid);
    stage_w<H, H>(Whh, sU, tid);
    stage_b<H>(bih, bhh, sB, tid);
    __syncthreads();

    u64 h2[H];
    float cA[H], cB[H];
    #pragma unroll
    for (int u = 0; u < H; u++) { h2[u] = 0ull; cA[u] = 0.f; cB[u] = 0.f; }

    const int* fin = L0 ? &prog1[31] : &prog2[layer - 1];
    int* fout = &prog2[layer];
    int avail = 0;

    for (int t = 0; t < TT; t++) {
        if (tid == 0) { while (avail <= t) avail = ld_acq(fin); }
        __syncthreads();

        u64 xv[DIN];
        if (L0) {  // from buf1[31], DIN=4, with RELU
            ulonglong2 r0 = *(ulonglong2*)&buf1[31][t][tid][0];
            ulonglong2 r1 = *(ulonglong2*)&buf1[31][t][tid][2];
            u64 raw[4] = { r0.x, r0.y, r1.x, r1.y };
            #pragma unroll
            for (int k = 0; k < 4; k++) {
                float a, b; unpack2(raw[k], a, b);
                xv[k] = pack2(fmaxf(a, 0.f), fmaxf(b, 0.f));
            }
        } else {   // from buf2[layer-1], DIN=8
            #pragma unroll
            for (int j = 0; j < 4; j++) {
                ulonglong2 r = *(ulonglong2*)&buf2[layer - 1][t][tid][2 * j];
                xv[2 * j] = r.x; xv[2 * j + 1] = r.y;
            }
        }
        u64 hn[H];
        #pragma unroll
        for (int u = 0; u < H; u++) {
            ulonglong2 b01 = *(ulonglong2*)&sB[u * 4];
            ulonglong2 b23 = *(ulonglong2*)&sB[u * 4 + 2];
            u64 ai = b01.x, af = b01.y, ag = b23.x, ao = b23.y;
            #pragma unroll
            for (int k = 0; k < DIN; k++) {
                ulonglong2 w01 = *(ulonglong2*)&sW[(u * DIN + k) * 4];
                ulonglong2 w23 = *(ulonglong2*)&sW[(u * DIN + k) * 4 + 2];
                ai = ffma2(xv[k], w01.x, ai); af = ffma2(xv[k], w01.y, af);
                ag = ffma2(xv[k], w23.x, ag); ao = ffma2(xv[k], w23.y, ao);
            }
            #pragma unroll
            for (int k = 0; k < H; k++) {
                ulonglong2 w01 = *(ulonglong2*)&sU[(u * H + k) * 4];
                ulonglong2 w23 = *(ulonglong2*)&sU[(u * H + k) * 4 + 2];
                ai = ffma2(h2[k], w01.x, ai); af = ffma2(h2[k], w01.y, af);
                ag = ffma2(h2[k], w23.x, ag); ao = ffma2(h2[k], w23.y, ao);
            }
            hn[u] = lstm_pair(ai, af, ag, ao, cA[u], cB[u]);
        }
        #pragma unroll
        for (int j = 0; j < 4; j++) {
            *(ulonglong2*)&buf2[layer][t][tid][2 * j] =
                make_ulonglong2(hn[2 * j], hn[2 * j + 1]);
            h2[2 * j] = hn[2 * j]; h2[2 * j + 1] = hn[2 * j + 1];
        }
        __syncthreads();
        if (tid == 0) { __threadfence(); st_rel(fout, t + 1); }
    }
}

// ------ Stack 3: H=16, block = 64-batch slice (32 pairs), 4 units/thread ------
template <int DIN, bool L0, bool LAST>
__device__ void run_stack3(const float* Wih, const float* Whh,
                           const float* bih, const float* bhh,
                           int layer, int slice, u64* sm,
                           const float* fcW, const float* fcb, float* out)
{
    const int H = 16, XP = DIN + 1;
    u64* sW = sm;                       // H*DIN*4
    u64* sU = sW + H * DIN * 4;         // 1024
    u64* sB = sU + H * H * 4;           // 64
    u64* xs = sB + 64;                  // 32*XP
    u64* hs = xs + 32 * XP;             // 32*17
    float* sfc = (float*)(hs + 32 * 17);

    int tid = threadIdx.x;
    int p = tid & 31, ug = tid >> 5;

    stage_w<H, DIN>(Wih, sW, tid);
    stage_w<H, H>(Whh, sU, tid);
    stage_b<H>(bih, bhh, sB, tid);
    if (LAST) {
        if (tid < 64) sfc[tid] = fcW[tid];
        if (tid < 4)  sfc[64 + tid] = fcb[tid];
    }
    for (int i = tid; i < 32 * 17; i += 128) hs[i] = 0ull;
    __syncthreads();

    float cA[4], cB[4];
    #pragma unroll
    for (int v = 0; v < 4; v++) { cA[v] = 0.f; cB[v] = 0.f; }

    const int* fin = L0 ? &prog2[63] : &prog3[layer - 1][slice];
    int avail = 0;

    for (int t = 0; t < TT; t++) {
        if (tid == 0) { while (avail <= t) avail = ld_acq(fin); }
        __syncthreads();                                      // bar1

        // stage x into smem (packed rows already); read prev h
        const u64* src = L0 ? &buf2[63][t][32 * slice][0]
                            : &buf3[layer - 1][t][32 * slice][0];
        for (int i = tid; i < 32 * DIN; i += 128) {
            u64 v = src[i];
            if (L0) {
                float a, b; unpack2(v, a, b);
                v = pack2(fmaxf(a, 0.f), fmaxf(b, 0.f));
            }
            xs[(i / DIN) * XP + (i % DIN)] = v;
        }
        u64 hr[H];
        #pragma unroll
        for (int k = 0; k < H; k++) hr[k] = hs[p * 17 + k];
        __syncthreads();                                      // bar2

        u64 xv[DIN];
        #pragma unroll
        for (int k = 0; k < DIN; k++) xv[k] = xs[p * XP + k];

        u64 hn[4];
        #pragma unroll
        for (int v = 0; v < 4; v++) {
            int u = ug * 4 + v;
            ulonglong2 b01 = *(ulonglong2*)&sB[u * 4];
            ulonglong2 b23 = *(ulonglong2*)&sB[u * 4 + 2];
            u64 ai = b01.x, af = b01.y, ag = b23.x, ao = b23.y;
            #pragma unroll
            for (int k = 0; k < DIN; k++) {
                ulonglong2 w01 = *(ulonglong2*)&sW[(u * DIN + k) * 4];
                ulonglong2 w23 = *(ulonglong2*)&sW[(u * DIN + k) * 4 + 2];
                ai = ffma2(xv[k], w01.x, ai); af = ffma2(xv[k], w01.y, af);
                ag = ffma2(xv[k], w23.x, ag); ao = ffma2(xv[k], w23.y, ao);
            }
            #pragma unroll
            for (int k = 0; k < H; k++) {
                ulonglong2 w01 = *(ulonglong2*)&sU[(u * H + k) * 4];
                ulonglong2 w23 = *(ulonglong2*)&sU[(u * H + k) * 4 + 2];
                ai = ffma2(hr[k], w01.x, ai); af = ffma2(hr[k], w01.y, af);
                ag = ffma2(hr[k], w23.x, ag); ao = ffma2(hr[k], w23.y, ao);
            }
            hn[v] = lstm_pair(ai, af, ag, ao, cA[v], cB[v]);
        }
        #pragma unroll
        for (int v = 0; v < 4; v++) hs[p * 17 + ug * 4 + v] = hn[v];
        if (!LAST) {
            *(ulonglong2*)&buf3[layer][t][32 * slice + p][ug * 4] =
                make_ulonglong2(hn[0], hn[1]);
            *(ulonglong2*)&buf3[layer][t][32 * slice + p][ug * 4 + 2] =
                make_ulonglong2(hn[2], hn[3]);
        }
        __syncthreads();                                      // bar3
        if (!LAST) {
            if (tid == 0) { __threadfence(); st_rel(&prog3[layer][slice], t + 1); }
        } else {
            if (tid < 64) {
                int pr = tid >> 1, hf = tid & 1;
                float o0 = sfc[64], o1 = sfc[65], o2 = sfc[66], o3 = sfc[67];
                #pragma unroll
                for (int k = 0; k < 16; k++) {
                    float hv = ((const float*)&hs[pr * 17 + k])[hf];
                    hv = fmaxf(hv, 0.f);
                    o0 += hv * sfc[k];
                    o1 += hv * sfc[16 + k];
                    o2 += hv * sfc[32 + k];
                    o3 += hv * sfc[48 + k];
                }
                *(float4*)&out[(t * 256 + slice * 64 + tid) * 4] =
                    make_float4(o0, o1, o2, o3);
            }
        }
    }
}

// ---------------- dispatch ----------------
__global__ void __launch_bounds__(128, 3) lstm_pipe(P27 P, float* out)
{
    __shared__ __align__(16) u64 sm[3240];
    int bid = blockIdx.x;
    if (bid < 32) {
        if (bid == 0)
            run_stack1<2, true>(P.p[1], P.p[2], P.p[3], P.p[4], P.p[0], 0, sm);
        else
            run_stack1<4, false>(P.p[5] + (bid - 1) * 64, P.p[6] + (bid - 1) * 64,
                                 P.p[7] + (bid - 1) * 16, P.p[8] + (bid - 1) * 16,
                                 (const float*)0, bid, sm);
    } else if (bid < 96) {
        int l = bid - 32;
        if (l == 0)
            run_stack2<4, true>(P.p[9], P.p[10], P.p[11], P.p[12], 0, sm);
        else
            run_stack2<8, false>(P.p[13] + (l - 1) * 256, P.p[14] + (l - 1) * 256,
                                 P.p[15] + (l - 1) * 32, P.p[16] + (l - 1) * 32,
                                 l, sm);
    } else {
        int idx = bid - 96;
        int l = idx >> 2, s = idx & 3;
        if (l == 0)
            run_stack3<8, true, false>(P.p[17], P.p[18], P.p[19], P.p[20],
                                       0, s, sm, (const float*)0, (const float*)0,
                                       (float*)0);
        else if (l < 63)
            run_stack3<16, false, false>(P.p[21] + (l - 1) * 1024,
                                         P.p[22] + (l - 1) * 1024,
                                         P.p[23] + (l - 1) * 64,
                                         P.p[24] + (l - 1) * 64,
                                         l, s, sm, (const float*)0, (const float*)0,
                                         (float*)0);
        else
            run_stack3<16, false, true>(P.p[21] + 62 * 1024, P.p[22] + 62 * 1024,
                                        P.p[23] + 62 * 64, P.p[24] + 62 * 64,
                                        63, s, sm, P.p[25], P.p[26], out);
    }
}

__global__ void reset_progress()
{
    int i = threadIdx.x;
    if (i < 32) prog1[i] = 0;
    if (i < 64) prog2[i] = 0;
    ((int*)prog3)[i] = 0;   // 256 entries
}

extern "C" void kernel_launch(void* const* d_in, const int* in_sizes, int n_in,
                              void* d_out, int out_size)
{
    P27 P;
    for (int i = 0; i < 27; i++) P.p[i] = (const float*)d_in[i];
    reset_progress<<<1, 256>>>();
    lstm_pipe<<<352, 128>>>(P, (float*)d_out);
}

// round 11
// speedup vs baseline: 1.3483x; 1.0291x over previous
#include <cuda_runtime.h>

#define TT 512
typedef unsigned long long u64;

__device__ u64 buf1[32][TT][128][4];
__device__ u64 buf2[64][TT][128][8];
__device__ u64 buf3[63][TT][128][16];
__device__ int prog1[32];
__device__ int prog2[64];
__device__ int prog3[64][4];

struct P27 { const float* p[27]; };

__device__ __forceinline__ int ld_acq(const int* p) {
    int v;
    asm volatile("ld.acquire.gpu.u32 %0, [%1];" : "=r"(v) : "l"(p) : "memory");
    return v;
}
__device__ __forceinline__ void st_rel(int* p, int v) {
    asm volatile("st.release.gpu.u32 [%0], %1;" :: "l"(p), "r"(v) : "memory");
}
__device__ __forceinline__ u64 ffma2(u64 a, u64 b, u64 c) {
    u64 d;
    asm("fma.rn.f32x2 %0, %1, %2, %3;" : "=l"(d) : "l"(a), "l"(b), "l"(c));
    return d;
}
__device__ __forceinline__ u64 pack2(float lo, float hi) {
    u64 d;
    asm("mov.b64 %0, {%1, %2};" : "=l"(d) : "f"(lo), "f"(hi));
    return d;
}
__device__ __forceinline__ void unpack2(u64 a, float& x, float& y) {
    asm("mov.b64 {%0, %1}, %2;" : "=f"(x), "=f"(y) : "l"(a));
}
__device__ __forceinline__ float sigf(float x) {
    return __fdividef(1.0f, 1.0f + __expf(-x));
}
__device__ __forceinline__ float tanhfast(float x) {
    return 1.0f - __fdividef(2.0f, __expf(2.0f * x) + 1.0f);
}
__device__ __forceinline__ u64 lstm_pair(u64 ai, u64 af, u64 ag, u64 ao,
                                         float& ca, float& cb) {
    float i0,i1,f0,f1,g0,g1,o0,o1;
    unpack2(ai,i0,i1); unpack2(af,f0,f1); unpack2(ag,g0,g1); unpack2(ao,o0,o1);
    float c0 = sigf(f0) * ca + sigf(i0) * tanhfast(g0);
    float c1 = sigf(f1) * cb + sigf(i1) * tanhfast(g1);
    ca = c0; cb = c1;
    return pack2(sigf(o0) * tanhfast(c0), sigf(o1) * tanhfast(c1));
}

// s[(u*DIN + k)*4 + g] = {w,w} with w = W[(g*H + u)*DIN + k]
template <int H, int DIN>
__device__ void stage_w(const float* W, u64* s, int tid) {
    for (int i = tid; i < 4 * H * DIN; i += 256) {
        int r = i / DIN, k = i - r * DIN;
        int g = r / H,  u = r - g * H;
        float w = W[i];
        s[(u * DIN + k) * 4 + g] = pack2(w, w);
    }
}
template <int H>
__device__ void stage_b(const float* bih, const float* bhh, u64* s, int tid) {
    for (int i = tid; i < 4 * H; i += 256) {
        int g = i / H, u = i - g * H;
        float b = bih[i] + bhh[i];
        s[u * 4 + g] = pack2(b, b);
    }
}

// ------------- Stack 1: H=4, 128 active threads (thread = batch pair) -------------
template <int DIN, bool L0>
__device__ void run_stack1(const float* Wih, const float* Whh,
                           const float* bih, const float* bhh,
                           const float* xin, int layer, u64* sm)
{
    const int H = 4;
    u64* sW = sm;
    u64* sU = sW + H * DIN * 4;
    u64* sB = sU + H * H * 4;
    int tid = threadIdx.x;
    stage_w<H, DIN>(Wih, sW, tid);
    stage_w<H, H>(Whh, sU, tid);
    stage_b<H>(bih, bhh, sB, tid);
    __syncthreads();

    u64 h2[H];
    float cA[H], cB[H];
    #pragma unroll
    for (int u = 0; u < H; u++) { h2[u] = 0ull; cA[u] = 0.f; cB[u] = 0.f; }

    const int* fin = L0 ? (const int*)0 : &prog1[layer - 1];
    int* fout = &prog1[layer];
    int avail = 0;

    for (int t = 0; t < TT; t++) {
        if (!L0) {
            if (tid == 0) { while (avail <= t) avail = ld_acq(fin); }
            __syncthreads();
        }
        if (tid < 128) {
            u64 xv[DIN];
            if (L0) {
                float2 a = *(const float2*)(xin + (t * 256 + 2 * tid) * 2);
                float2 b = *(const float2*)(xin + (t * 256 + 2 * tid + 1) * 2);
                xv[0] = pack2(a.x, b.x); xv[1] = pack2(a.y, b.y);
            } else {
                ulonglong2 r0 = *(ulonglong2*)&buf1[layer - 1][t][tid][0];
                ulonglong2 r1 = *(ulonglong2*)&buf1[layer - 1][t][tid][2];
                xv[0] = r0.x; xv[1] = r0.y;
                if (DIN == 4) { xv[2] = r1.x; xv[3] = r1.y; }
            }
            u64 hn[H];
            #pragma unroll
            for (int u = 0; u < H; u++) {
                ulonglong2 b01 = *(ulonglong2*)&sB[u * 4];
                ulonglong2 b23 = *(ulonglong2*)&sB[u * 4 + 2];
                u64 ai = b01.x, af = b01.y, ag = b23.x, ao = b23.y;
                #pragma unroll
                for (int k = 0; k < DIN; k++) {
                    ulonglong2 w01 = *(ulonglong2*)&sW[(u * DIN + k) * 4];
                    ulonglong2 w23 = *(ulonglong2*)&sW[(u * DIN + k) * 4 + 2];
                    ai = ffma2(xv[k], w01.x, ai); af = ffma2(xv[k], w01.y, af);
                    ag = ffma2(xv[k], w23.x, ag); ao = ffma2(xv[k], w23.y, ao);
                }
                #pragma unroll
                for (int k = 0; k < H; k++) {
                    ulonglong2 w01 = *(ulonglong2*)&sU[(u * H + k) * 4];
                    ulonglong2 w23 = *(ulonglong2*)&sU[(u * H + k) * 4 + 2];
                    ai = ffma2(h2[k], w01.x, ai); af = ffma2(h2[k], w01.y, af);
                    ag = ffma2(h2[k], w23.x, ag); ao = ffma2(h2[k], w23.y, ao);
                }
                hn[u] = lstm_pair(ai, af, ag, ao, cA[u], cB[u]);
            }
            #pragma unroll
            for (int u = 0; u < H; u++) h2[u] = hn[u];
            *(ulonglong2*)&buf1[layer][t][tid][0] = make_ulonglong2(hn[0], hn[1]);
            *(ulonglong2*)&buf1[layer][t][tid][2] = make_ulonglong2(hn[2], hn[3]);
        }
        __syncthreads();
        if (tid == 0) st_rel(fout, t + 1);
    }
}

// ------ Stack 2: H=8, 256 threads: pair p = tid&127, unit-group ug = tid>>7 ------
template <int DIN, bool L0>
__device__ void run_stack2(const float* Wih, const float* Whh,
                           const float* bih, const float* bhh,
                           int layer, u64* sm)
{
    const int H = 8, HP = 9;
    u64* sW = sm;                        // H*DIN*4
    u64* sU = sW + H * DIN * 4;          // 256
    u64* sB = sU + H * H * 4;            // 32
    u64* hsb = sB + 32;                  // 2 * 128 * HP
    int tid = threadIdx.x;
    int p = tid & 127, ug = tid >> 7;

    stage_w<H, DIN>(Wih, sW, tid);
    stage_w<H, H>(Whh, sU, tid);
    stage_b<H>(bih, bhh, sB, tid);
    for (int i = tid; i < 2 * 128 * HP; i += 256) hsb[i] = 0ull;
    __syncthreads();

    float cA[4], cB[4];
    #pragma unroll
    for (int v = 0; v < 4; v++) { cA[v] = 0.f; cB[v] = 0.f; }

    const int* fin = L0 ? &prog1[31] : &prog2[layer - 1];
    int* fout = &prog2[layer];
    int avail = 0;

    for (int t = 0; t < TT; t++) {
        if (tid == 0) { while (avail <= t) avail = ld_acq(fin); }
        __syncthreads();                                    // bar1

        const u64* hsp = hsb + (t & 1) * 128 * HP;
        u64* hsn = hsb + ((t + 1) & 1) * 128 * HP;

        u64 xv[DIN];
        if (L0) {
            ulonglong2 r0 = *(ulonglong2*)&buf1[31][t][p][0];
            ulonglong2 r1 = *(ulonglong2*)&buf1[31][t][p][2];
            u64 raw[4] = { r0.x, r0.y, r1.x, r1.y };
            #pragma unroll
            for (int k = 0; k < 4; k++) {
                float a, b; unpack2(raw[k], a, b);
                xv[k] = pack2(fmaxf(a, 0.f), fmaxf(b, 0.f));
            }
        } else {
            #pragma unroll
            for (int j = 0; j < 4; j++) {
                ulonglong2 r = *(ulonglong2*)&buf2[layer - 1][t][p][2 * j];
                xv[2 * j] = r.x; xv[2 * j + 1] = r.y;
            }
        }
        u64 hr[H];
        #pragma unroll
        for (int k = 0; k < H; k++) hr[k] = hsp[p * HP + k];

        u64 hn[4];
        #pragma unroll
        for (int v = 0; v < 4; v++) {
            int u = ug * 4 + v;
            ulonglong2 b01 = *(ulonglong2*)&sB[u * 4];
            ulonglong2 b23 = *(ulonglong2*)&sB[u * 4 + 2];
            u64 ai = b01.x, af = b01.y, ag = b23.x, ao = b23.y;
            #pragma unroll
            for (int k = 0; k < DIN; k++) {
                ulonglong2 w01 = *(ulonglong2*)&sW[(u * DIN + k) * 4];
                ulonglong2 w23 = *(ulonglong2*)&sW[(u * DIN + k) * 4 + 2];
                ai = ffma2(xv[k], w01.x, ai); af = ffma2(xv[k], w01.y, af);
                ag = ffma2(xv[k], w23.x, ag); ao = ffma2(xv[k], w23.y, ao);
            }
            #pragma unroll
            for (int k = 0; k < H; k++) {
                ulonglong2 w01 = *(ulonglong2*)&sU[(u * H + k) * 4];
                ulonglong2 w23 = *(ulonglong2*)&sU[(u * H + k) * 4 + 2];
                ai = ffma2(hr[k], w01.x, ai); af = ffma2(hr[k], w01.y, af);
                ag = ffma2(hr[k], w23.x, ag); ao = ffma2(hr[k], w23.y, ao);
            }
            hn[v] = lstm_pair(ai, af, ag, ao, cA[v], cB[v]);
        }
        #pragma unroll
        for (int v = 0; v < 4; v++) hsn[p * HP + ug * 4 + v] = hn[v];
        *(ulonglong2*)&buf2[layer][t][p][ug * 4]     = make_ulonglong2(hn[0], hn[1]);
        *(ulonglong2*)&buf2[layer][t][p][ug * 4 + 2] = make_ulonglong2(hn[2], hn[3]);
        __syncthreads();                                    // bar2
        if (tid == 0) st_rel(fout, t + 1);
    }
}

// --- Stack 3: H=16, 256 threads: pair p = tid&31 (64-batch slice), ug = tid>>5 ---
template <int DIN, bool L0, bool LAST>
__device__ void run_stack3(const float* Wih, const float* Whh,
                           const float* bih, const float* bhh,
                           int layer, int slice, u64* sm,
                           const float* fcW, const float* fcb, float* out)
{
    const int H = 16, HP = 17;
    u64* sW = sm;                        // H*DIN*4
    u64* sU = sW + H * DIN * 4;          // 1024
    u64* sB = sU + H * H * 4;            // 64
    u64* hsb = sB + 64;                  // 2 * 32 * HP
    float* sfc = (float*)(hsb + 2 * 32 * HP);

    int tid = threadIdx.x;
    int p = tid & 31, ug = tid >> 5;     // 8 unit-groups x 2 units

    stage_w<H, DIN>(Wih, sW, tid);
    stage_w<H, H>(Whh, sU, tid);
    stage_b<H>(bih, bhh, sB, tid);
    if (LAST) {
        if (tid < 64) sfc[tid] = fcW[tid];
        if (tid < 4)  sfc[64 + tid] = fcb[tid];
    }
    for (int i = tid; i < 2 * 32 * HP; i += 256) hsb[i] = 0ull;
    __syncthreads();

    float cA[2], cB[2];
    cA[0] = cA[1] = cB[0] = cB[1] = 0.f;

    const int* fin = L0 ? &prog2[63] : &prog3[layer - 1][slice];
    int avail = 0;

    for (int t = 0; t < TT; t++) {
        if (tid == 0) { while (avail <= t) avail = ld_acq(fin); }
        __syncthreads();                                    // bar1

        const u64* hsp = hsb + (t & 1) * 32 * HP;
        u64* hsn = hsb + ((t + 1) & 1) * 32 * HP;

        // direct x load (L1-broadcast across the 8 ug-warps)
        u64 xv[DIN];
        const u64* src = L0 ? &buf2[63][t][32 * slice + p][0]
                            : &buf3[layer - 1][t][32 * slice + p][0];
        #pragma unroll
        for (int j = 0; j < DIN / 2; j++) {
            ulonglong2 r = *(const ulonglong2*)&src[2 * j];
            if (L0) {
                float a, b;
                unpack2(r.x, a, b); xv[2*j]   = pack2(fmaxf(a,0.f), fmaxf(b,0.f));
                unpack2(r.y, a, b); xv[2*j+1] = pack2(fmaxf(a,0.f), fmaxf(b,0.f));
            } else { xv[2*j] = r.x; xv[2*j+1] = r.y; }
        }

        int u0 = ug * 2;
        u64 acc[2][4];
        #pragma unroll
        for (int v = 0; v < 2; v++) {
            ulonglong2 b01 = *(ulonglong2*)&sB[(u0 + v) * 4];
            ulonglong2 b23 = *(ulonglong2*)&sB[(u0 + v) * 4 + 2];
            acc[v][0] = b01.x; acc[v][1] = b01.y; acc[v][2] = b23.x; acc[v][3] = b23.y;
        }
        #pragma unroll
        for (int k = 0; k < DIN; k++) {
            u64 xk = xv[k];
            #pragma unroll
            for (int v = 0; v < 2; v++) {
                ulonglong2 w01 = *(ulonglong2*)&sW[((u0 + v) * DIN + k) * 4];
                ulonglong2 w23 = *(ulonglong2*)&sW[((u0 + v) * DIN + k) * 4 + 2];
                acc[v][0] = ffma2(xk, w01.x, acc[v][0]);
                acc[v][1] = ffma2(xk, w01.y, acc[v][1]);
                acc[v][2] = ffma2(xk, w23.x, acc[v][2]);
                acc[v][3] = ffma2(xk, w23.y, acc[v][3]);
            }
        }
        #pragma unroll
        for (int k = 0; k < H; k++) {
            u64 hk = hsp[p * HP + k];
            #pragma unroll
            for (int v = 0; v < 2; v++) {
                ulonglong2 w01 = *(ulonglong2*)&sU[((u0 + v) * H + k) * 4];
                ulonglong2 w23 = *(ulonglong2*)&sU[((u0 + v) * H + k) * 4 + 2];
                acc[v][0] = ffma2(hk, w01.x, acc[v][0]);
                acc[v][1] = ffma2(hk, w01.y, acc[v][1]);
                acc[v][2] = ffma2(hk, w23.x, acc[v][2]);
                acc[v][3] = ffma2(hk, w23.y, acc[v][3]);
            }
        }
        u64 hn0 = lstm_pair(acc[0][0], acc[0][1], acc[0][2], acc[0][3], cA[0], cB[0]);
        u64 hn1 = lstm_pair(acc[1][0], acc[1][1], acc[1][2], acc[1][3], cA[1], cB[1]);

        hsn[p * HP + u0]     = hn0;
        hsn[p * HP + u0 + 1] = hn1;
        if (!LAST)
            *(ulonglong2*)&buf3[layer][t][32 * slice + p][u0] =
                make_ulonglong2(hn0, hn1);
        __syncthreads();                                    // bar2
        if (!LAST) {
            if (tid == 0) st_rel(&prog3[layer][slice], t + 1);
        } else {
            if (tid < 64) {
                int pr = tid >> 1, hf = tid & 1;
                float o0 = sfc[64], o1 = sfc[65], o2 = sfc[66], o3 = sfc[67];
                #pragma unroll
                for (int k = 0; k < 16; k++) {
                    float hv = ((const float*)&hsn[pr * HP + k])[hf];
                    hv = fmaxf(hv, 0.f);
                    o0 += hv * sfc[k];
                    o1 += hv * sfc[16 + k];
                    o2 += hv * sfc[32 + k];
                    o3 += hv * sfc[48 + k];
                }
                *(float4*)&out[(t * 256 + slice * 64 + tid) * 4] =
                    make_float4(o0, o1, o2, o3);
            }
        }
    }
}

// ---------------- dispatch ----------------
__global__ void __launch_bounds__(256, 3) lstm_pipe(P27 P, float* out)
{
    __shared__ __align__(16) u64 sm[3240];
    int bid = blockIdx.x;
    if (bid < 32) {
        if (bid == 0)
            run_stack1<2, true>(P.p[1], P.p[2], P.p[3], P.p[4], P.p[0], 0, sm);
        else
            run_stack1<4, false>(P.p[5] + (bid - 1) * 64, P.p[6] + (bid - 1) * 64,
                                 P.p[7] + (bid - 1) * 16, P.p[8] + (bid - 1) * 16,
                                 (const float*)0, bid, sm);
    } else if (bid < 96) {
        int l = bid - 32;
        if (l == 0)
            run_stack2<4, true>(P.p[9], P.p[10], P.p[11], P.p[12], 0, sm);
        else
            run_stack2<8, false>(P.p[13] + (l - 1) * 256, P.p[14] + (l - 1) * 256,
                                 P.p[15] + (l - 1) * 32, P.p[16] + (l - 1) * 32,
                                 l, sm);
    } else {
        int idx = bid - 96;
        int l = idx >> 2, s = idx & 3;
        if (l == 0)
            run_stack3<8, true, false>(P.p[17], P.p[18], P.p[19], P.p[20],
                                       0, s, sm, (const float*)0, (const float*)0,
                                       (float*)0);
        else if (l < 63)
            run_stack3<16, false, false>(P.p[21] + (l - 1) * 1024,
                                         P.p[22] + (l - 1) * 1024,
                                         P.p[23] + (l - 1) * 64,
                                         P.p[24] + (l - 1) * 64,
                                         l, s, sm, (const float*)0, (const float*)0,
                                         (float*)0);
        else
            run_stack3<16, false, true>(P.p[21] + 62 * 1024, P.p[22] + 62 * 1024,
                                        P.p[23] + 62 * 64, P.p[24] + 62 * 64,
                                        63, s, sm, P.p[25], P.p[26], out);
    }
}

__global__ void reset_progress()
{
    int i = threadIdx.x;
    if (i < 32) prog1[i] = 0;
    if (i < 64) prog2[i] = 0;
    ((int*)prog3)[i] = 0;
}

extern "C" void kernel_launch(void* const* d_in, const int* in_sizes, int n_in,
                              void* d_out, int out_size)
{
    P27 P;
    for (int i = 0; i < 27; i++) P.p[i] = (const float*)d_in[i];
    reset_progress<<<1, 256>>>();
    lstm_pipe<<<352, 256>>>(P, (float*)d_out);
}